// round 11
// baseline (speedup 1.0000x reference)
#include <cuda_runtime.h>
#include <cuda_fp16.h>
#include <math.h>
#include <stdint.h>

// Problem constants
#define S_LEN  2048
#define HID    2048
#define NH     16
#define NKV    4
#define HD     128
#define KVDIM  512
#define QKVW   3072
#define K0     2048
#define KC2    (2*K0)      // 4096: B-side hi|lo concatenated K

// Scratch (device globals — no allocation allowed)
__device__ float  g_part[2 * S_LEN * QKVW];      // split-term partials (hi, lo)
__device__ __half g_attnh[S_LEN * HID];          // attention output (fp16, A-side)
__device__ __half g_Xh[S_LEN * K0];              // X rounded fp16
__device__ __half g_Wqkv2[QKVW * KC2];           // Wq|Wk|Wv  [3072][hi|lo 4096]
__device__ __half g_Wo2[HID * KC2];              // Wo [2048][hi|lo 4096]
// attention operands
__device__ __half g_Qh[S_LEN * HID];             // scaled+rope q, rounded
__device__ __half g_Khi[S_LEN * KVDIM];
__device__ __half g_Klo[S_LEN * KVDIM];
__device__ __half g_Vhi[S_LEN * KVDIM];
__device__ __half g_Vlo[S_LEN * KVDIM];

// ---------------------------------------------------------------------------
// helpers
// ---------------------------------------------------------------------------
__device__ __forceinline__ uint32_t smem_u32(const void* p) {
    uint32_t a;
    asm("{ .reg .u64 t; cvta.to.shared.u64 t, %1; cvt.u32.u64 %0, t; }" : "=r"(a) : "l"(p));
    return a;
}
__device__ __forceinline__ void cpasync16(uint32_t s, const void* g) {
    asm volatile("cp.async.cg.shared.global [%0], [%1], 16;" :: "r"(s), "l"(g) : "memory");
}
__device__ __forceinline__ uint32_t swz(uint32_t off) {        // SW128 XOR swizzle
    return off ^ ((off >> 3) & 0x70);
}
__device__ __forceinline__ void ldsm4(uint32_t* r, uint32_t addr) {
    asm volatile("ldmatrix.sync.aligned.m8n8.x4.shared.b16 {%0,%1,%2,%3}, [%4];"
                 : "=r"(r[0]), "=r"(r[1]), "=r"(r[2]), "=r"(r[3]) : "r"(addr));
}
__device__ __forceinline__ void ldsm4t(uint32_t* r, uint32_t addr) {
    asm volatile("ldmatrix.sync.aligned.m8n8.x4.trans.shared.b16 {%0,%1,%2,%3}, [%4];"
                 : "=r"(r[0]), "=r"(r[1]), "=r"(r[2]), "=r"(r[3]) : "r"(addr));
}
__device__ __forceinline__ void mma_f16(float* d, const uint32_t* a, const uint32_t* b) {
    asm volatile(
        "mma.sync.aligned.m16n8k16.row.col.f32.f16.f16.f32 "
        "{%0,%1,%2,%3}, {%4,%5,%6,%7}, {%8,%9}, {%0,%1,%2,%3};"
        : "+f"(d[0]), "+f"(d[1]), "+f"(d[2]), "+f"(d[3])
        : "r"(a[0]), "r"(a[1]), "r"(a[2]), "r"(a[3]), "r"(b[0]), "r"(b[1]));
}
__device__ __forceinline__ uint32_t pack_h2(float lo, float hi) {
    __half2 t = __floats2half2_rn(lo, hi);
    return *reinterpret_cast<uint32_t*>(&t);
}

// ---------------------------------------------------------------------------
// One merged conversion kernel.
// Combined row space (each row 2048 fp32):
//   [0,2048)    Wq  -> g_Wqkv2 row r        (hi|lo split)
//   [2048,2560) Wk  -> g_Wqkv2 row r        (hi|lo split)
//   [2560,3072) Wv  -> g_Wqkv2 row r        (hi|lo split)
//   [3072,5120) Wo  -> g_Wo2  row r-3072    (hi|lo split)
//   [5120,7168) X   -> g_Xh                 (plain round)
// ---------------------------------------------------------------------------
#define CONV_N4 ((QKVW + HID + S_LEN) * (K0 / 4))

__global__ void convert_all(const float4* __restrict__ Wq, const float4* __restrict__ Wk,
                            const float4* __restrict__ Wv, const float4* __restrict__ Wo,
                            const float4* __restrict__ X) {
    int idx = blockIdx.x * 256 + threadIdx.x;
    if (idx >= CONV_N4) return;
    int e = idx * 4;
    int r = e >> 11;
    int c = e & (K0 - 1);

    if (r >= QKVW + HID) {           // X: plain fp16 round
        int xr = r - (QKVW + HID);
        float4 v = X[((size_t)xr * K0 + c) >> 2];
        __half2* o = (__half2*)(g_Xh + (size_t)xr * K0 + c);
        o[0] = __floats2half2_rn(v.x, v.y);
        o[1] = __floats2half2_rn(v.z, v.w);
        return;
    }

    const float4* src;
    __half* dst;
    if (r < HID) {                   // Wq
        src = Wq + (((size_t)r * K0 + c) >> 2);
        dst = g_Wqkv2 + (size_t)r * KC2;
    } else if (r < HID + KVDIM) {    // Wk
        src = Wk + (((size_t)(r - HID) * K0 + c) >> 2);
        dst = g_Wqkv2 + (size_t)r * KC2;
    } else if (r < QKVW) {           // Wv
        src = Wv + (((size_t)(r - HID - KVDIM) * K0 + c) >> 2);
        dst = g_Wqkv2 + (size_t)r * KC2;
    } else {                         // Wo
        src = Wo + (((size_t)(r - QKVW) * K0 + c) >> 2);
        dst = g_Wo2 + (size_t)(r - QKVW) * KC2;
    }
    float4 v = *src;
    __half2 h01 = __floats2half2_rn(v.x, v.y);
    __half2 h23 = __floats2half2_rn(v.z, v.w);
    __half2 l01 = __floats2half2_rn(v.x - __low2float(h01), v.y - __high2float(h01));
    __half2 l23 = __floats2half2_rn(v.z - __low2float(h23), v.w - __high2float(h23));
    __half2* oh = (__half2*)(dst + c);
    __half2* ol = (__half2*)(dst + K0 + c);
    oh[0] = h01; oh[1] = h23;
    ol[0] = l01; ol[1] = l23;
}

// ---------------------------------------------------------------------------
// fp16 HMMA GEMM (single variant): C[bm+128, bn+128] = A B'^T over kb range.
// A column wraps mod K0. CTA 128x128, KB=64, 8 warps (2x4), warp tile 64x32,
// 3-stage cp.async, 98KB smem -> 2 CTAs/SM.
// grid.z = split index: kb0 = z*nkb, C += z*zstride (z-extent 1 => plain GEMM).
// ---------------------------------------------------------------------------
#define KB      64
#define STG     32768               // stage: A 16KB + B 16KB
#define GEMM_SMEM (3 * STG)         // 98304

__global__ __launch_bounds__(256)
void gemm_mma(const __half* __restrict__ A, const __half* __restrict__ B,
              float* __restrict__ C, int ldc, int nkb, size_t zstride) {
    extern __shared__ char dsm[];
    const uint32_t base = smem_u32(dsm);
    const int tid  = threadIdx.x;
    const int wid  = tid >> 5;
    const int lane = tid & 31;
    const int wm   = wid >> 2;          // 0..1
    const int wn   = wid & 3;           // 0..3
    const int quad = lane >> 3;
    const int l8   = lane & 7;
    const int bm = blockIdx.y * 128;
    const int bn = blockIdx.x * 128;
    const int kb0 = blockIdx.z * nkb;
    C += (size_t)blockIdx.z * zstride;

    const __half* Abase = A + (size_t)bm * K0;
    const __half* Bbase = B + (size_t)bn * KC2;

    float acc[4][4][4];
#pragma unroll
    for (int i = 0; i < 4; i++)
#pragma unroll
        for (int j = 0; j < 4; j++)
#pragma unroll
            for (int v = 0; v < 4; v++) acc[i][j][v] = 0.f;

    int a_row[4], b_row[2];
#pragma unroll
    for (int mi = 0; mi < 4; mi++) a_row[mi] = wm * 64 + mi * 16 + (quad & 1) * 8 + l8;
#pragma unroll
    for (int n2 = 0; n2 < 2; n2++) b_row[n2] = wn * 32 + n2 * 16 + (quad >> 1) * 8 + l8;
    const int a_koff = (quad >> 1) * 16;
    const int b_koff = (quad & 1) * 16;

    const int ld_r = tid >> 3;          // 0..31
    const int ld_c = (tid & 7) * 8;

    auto issue_loads = [&](int kb, int buf) {
        const int a_col = (kb & 31) * KB + ld_c;     // wrap A over K0
        const __half* ag = Abase + (size_t)ld_r * K0 + a_col;
        const __half* bg = Bbase + (size_t)ld_r * KC2 + kb * KB + ld_c;
        const uint32_t sa = base + buf * STG;
        const uint32_t sb = sa + 16384;
#pragma unroll
        for (int i = 0; i < 4; i++) {
            uint32_t s = swz((uint32_t)((ld_r + i * 32) * 128 + ld_c * 2));
            cpasync16(sa + s, ag + (size_t)i * 32 * K0);
            cpasync16(sb + s, bg + (size_t)i * 32 * KC2);
        }
        asm volatile("cp.async.commit_group;" ::: "memory");
    };

    issue_loads(kb0, 0);
    issue_loads(kb0 + 1, 1);

    for (int t = 0; t < nkb; t++) {
        const int buf = t % 3;
        if (t + 2 < nkb) {
            issue_loads(kb0 + t + 2, (t + 2) % 3);
            asm volatile("cp.async.wait_group 2;" ::: "memory");
        } else if (t + 1 < nkb) {
            asm volatile("cp.async.wait_group 1;" ::: "memory");
        } else {
            asm volatile("cp.async.wait_group 0;" ::: "memory");
        }
        __syncthreads();

        const uint32_t As = base + buf * STG;
        const uint32_t Bs = As + 16384;
#pragma unroll
        for (int ks = 0; ks < 4; ks++) {
            uint32_t af[4][4], bf[2][4];
#pragma unroll
            for (int mi = 0; mi < 4; mi++)
                ldsm4(af[mi], As + swz((uint32_t)(a_row[mi] * 128 + ks * 32 + a_koff)));
#pragma unroll
            for (int n2 = 0; n2 < 2; n2++)
                ldsm4(bf[n2], Bs + swz((uint32_t)(b_row[n2] * 128 + ks * 32 + b_koff)));
#pragma unroll
            for (int mi = 0; mi < 4; mi++) {
#pragma unroll
                for (int ni = 0; ni < 4; ni++) {
                    uint32_t bb[2] = { bf[ni >> 1][(ni & 1) * 2], bf[ni >> 1][(ni & 1) * 2 + 1] };
                    mma_f16(acc[mi][ni], af[mi], bb);
                }
            }
        }
        __syncthreads();
    }

    const int er = lane >> 2;
    const int ec = (lane & 3) * 2;
#pragma unroll
    for (int mi = 0; mi < 4; mi++) {
        int row0 = bm + wm * 64 + mi * 16 + er;
#pragma unroll
        for (int ni = 0; ni < 4; ni++) {
            int col = bn + wn * 32 + ni * 8 + ec;
            *(float2*)(C + (size_t)row0 * ldc + col) = make_float2(acc[mi][ni][0], acc[mi][ni][1]);
            *(float2*)(C + (size_t)(row0 + 8) * ldc + col) = make_float2(acc[mi][ni][2], acc[mi][ni][3]);
        }
    }
}

// ---------------------------------------------------------------------------
// Fused partial-sum + RoPE + fp16 split into attention operands.
// grid (S, 24), block 64. h 0..15: Q (rope+scale, round); 16..19: K (rope,
// split); 20..23: V (split).  qkv value = p0 + p1 (the two GEMM terms).
// ---------------------------------------------------------------------------
__global__ void rope_sum(const float* __restrict__ p0, const float* __restrict__ p1) {
    const int s = blockIdx.x;
    const int h = blockIdx.y;
    const int i = threadIdx.x;       // 0..63
    const float sscale = 0.08838834764831845f;
    const int col = (h < NH) ? h * HD : (HID + (h - NH) * HD);   // K heads at HID+, V at HID+KVDIM+
    const int col2 = (h < NH + NKV) ? col : (HID + KVDIM + (h - NH - NKV) * HD);
    const size_t o0 = (size_t)s * QKVW + ((h < NH + NKV) ? col : col2);

    size_t i0 = o0 + i, i1 = o0 + i + 64;
    float x0 = p0[i0] + p1[i0];
    float x1 = p0[i1] + p1[i1];

    if (h < NH) {
        float freq = powf(10000.0f, -(float)(2 * i) / (float)HD);
        float sn, cs;
        sincosf((float)s * freq, &sn, &cs);
        float y0 = (x0 * cs - x1 * sn) * sscale;
        float y1 = (x1 * cs + x0 * sn) * sscale;
        __half* q = g_Qh + (size_t)s * HID + h * HD;
        q[i] = __float2half(y0);
        q[i + 64] = __float2half(y1);
    } else if (h < NH + NKV) {
        float freq = powf(10000.0f, -(float)(2 * i) / (float)HD);
        float sn, cs;
        sincosf((float)s * freq, &sn, &cs);
        float y0 = x0 * cs - x1 * sn;
        float y1 = x1 * cs + x0 * sn;
        size_t o = (size_t)s * KVDIM + (h - NH) * HD;
        __half h0 = __float2half(y0), h1 = __float2half(y1);
        g_Khi[o + i] = h0;       g_Klo[o + i] = __float2half(y0 - __half2float(h0));
        g_Khi[o + i + 64] = h1;  g_Klo[o + i + 64] = __float2half(y1 - __half2float(h1));
    } else {
        size_t o = (size_t)s * KVDIM + (h - NH - NKV) * HD;
        __half h0 = __float2half(x0), h1 = __float2half(x1);
        g_Vhi[o + i] = h0;       g_Vlo[o + i] = __float2half(x0 - __half2float(h0));
        g_Vhi[o + i + 64] = h1;  g_Vlo[o + i + 64] = __float2half(x1 - __half2float(h1));
    }
}

// ---------------------------------------------------------------------------
// HMMA flash attention (causal, GQA), fp16 2-term (unchanged, proven)
// ---------------------------------------------------------------------------
#define Q_OFF 0
#define KVB_OFF(b) (32768 + (b) * 65536)
#define KHI_O 0
#define KLO_O 16384
#define VHI_O 32768
#define VLO_O 49152
#define FLASH_SMEM 163840

__global__ __launch_bounds__(256)
void flash_mma(const __half* __restrict__ Qp,
               const __half* __restrict__ Kh, const __half* __restrict__ Kl,
               const __half* __restrict__ Vh, const __half* __restrict__ Vl,
               __half* __restrict__ attn_out) {
    extern __shared__ char dsm[];
    const uint32_t base = smem_u32(dsm);
    const int tid  = threadIdx.x;
    const int lane = tid & 31;
    const int warp = tid >> 5;
    const int qi   = (int)gridDim.x - 1 - (int)blockIdx.x;   // big tiles first
    const int h    = blockIdx.y;
    const int kvh  = h >> 2;
    const int wrow = warp * 16;
    const int nt   = 2 * qi + 2;

    {
        const int rr = tid >> 4;
        const int cc = (tid & 15) * 8;
        const int panel = cc >> 6;
        const int col = cc & 63;
        const __half* qg = Qp + (size_t)(qi * 128) * HID + h * HD + cc;
#pragma unroll
        for (int i = 0; i < 8; i++) {
            int r = rr + i * 16;
            uint32_t d = panel * 16384 + swz((uint32_t)(r * 128 + col * 2));
            cpasync16(base + Q_OFF + d, qg + (size_t)r * HID);
        }
    }
    auto issue_kv = [&](int kb, int buf) {
        const int rr = tid >> 4;
        const int cc = (tid & 15) * 8;
        const int panel = cc >> 6;
        const int col = cc & 63;
        const uint32_t kvb = base + KVB_OFF(buf);
#pragma unroll
        for (int i = 0; i < 4; i++) {
            int r = rr + i * 16;
            uint32_t d = panel * 8192 + swz((uint32_t)(r * 128 + col * 2));
            size_t g = (size_t)(kb * 64 + r) * KVDIM + kvh * HD + cc;
            cpasync16(kvb + KHI_O + d, Kh + g);
            cpasync16(kvb + KLO_O + d, Kl + g);
            cpasync16(kvb + VHI_O + d, Vh + g);
            cpasync16(kvb + VLO_O + d, Vl + g);
        }
        asm volatile("cp.async.commit_group;" ::: "memory");
    };
    issue_kv(0, 0);
    asm volatile("cp.async.wait_group 0;" ::: "memory");
    __syncthreads();

    auto ldQ = [&](int ks, uint32_t* a) {
        int row = wrow + (lane & 15);
        int kc = (16 * ks) & 63;
        uint32_t addr = base + Q_OFF + (ks >> 2) * 16384 +
                        swz((uint32_t)(row * 128 + (kc + (lane >> 4) * 8) * 2));
        ldsm4(a, addr);
    };
    auto ldK = [&](uint32_t arr, int ks, int nb, uint32_t* b) {
        int row = nb * 16 + (lane & 7) + ((lane >> 4) << 3);
        int kc = (16 * ks) & 63;
        int kadd = ((lane >> 3) & 1) * 8;
        uint32_t addr = base + arr + (ks >> 2) * 8192 +
                        swz((uint32_t)(row * 128 + (kc + kadd) * 2));
        ldsm4(b, addr);
    };
    auto ldV = [&](uint32_t arr, int ks, int db, uint32_t* b) {
        int row = ks * 16 + (lane & 7) + (((lane >> 3) & 1) << 3);
        int dc = (16 * db) & 63;
        int dadd = (lane >> 4) * 8;
        uint32_t addr = base + arr + (db >> 2) * 8192 +
                        swz((uint32_t)(row * 128 + (dc + dadd) * 2));
        ldsm4t(b, addr);
    };

    float oacc[16][4];
#pragma unroll
    for (int i = 0; i < 16; i++)
#pragma unroll
        for (int v = 0; v < 4; v++) oacc[i][v] = 0.f;
    float ml[2] = {-1e30f, -1e30f};
    float ll[2] = {0.f, 0.f};

    for (int kb = 0; kb < nt; kb++) {
        const int buf = kb & 1;
        if (kb + 1 < nt) {
            issue_kv(kb + 1, buf ^ 1);
            asm volatile("cp.async.wait_group 1;" ::: "memory");
        } else {
            asm volatile("cp.async.wait_group 0;" ::: "memory");
        }
        __syncthreads();

        const uint32_t kvb = KVB_OFF(buf);

        float pacc[8][4];
#pragma unroll
        for (int i = 0; i < 8; i++)
#pragma unroll
            for (int v = 0; v < 4; v++) pacc[i][v] = 0.f;

#pragma unroll
        for (int ks = 0; ks < 8; ks++) {
            uint32_t aq[4];
            ldQ(ks, aq);
#pragma unroll
            for (int nb = 0; nb < 4; nb++) {
                uint32_t bh[4], bl[4];
                ldK(kvb + KHI_O, ks, nb, bh);
                ldK(kvb + KLO_O, ks, nb, bl);
                mma_f16(pacc[2 * nb],     aq, bh);
                mma_f16(pacc[2 * nb + 1], aq, bh + 2);
                mma_f16(pacc[2 * nb],     aq, bl);
                mma_f16(pacc[2 * nb + 1], aq, bl + 2);
            }
        }

        if (kb >= 2 * qi) {
            int r0 = qi * 128 + wrow + (lane >> 2);
#pragma unroll
            for (int ni = 0; ni < 8; ni++) {
                int c0 = kb * 64 + ni * 8 + (lane & 3) * 2;
                if (c0     > r0)     pacc[ni][0] = -1e30f;
                if (c0 + 1 > r0)     pacc[ni][1] = -1e30f;
                if (c0     > r0 + 8) pacc[ni][2] = -1e30f;
                if (c0 + 1 > r0 + 8) pacc[ni][3] = -1e30f;
            }
        }

        float mx0 = -1e30f, mx1 = -1e30f;
#pragma unroll
        for (int ni = 0; ni < 8; ni++) {
            mx0 = fmaxf(mx0, fmaxf(pacc[ni][0], pacc[ni][1]));
            mx1 = fmaxf(mx1, fmaxf(pacc[ni][2], pacc[ni][3]));
        }
        mx0 = fmaxf(mx0, __shfl_xor_sync(0xffffffffu, mx0, 1));
        mx0 = fmaxf(mx0, __shfl_xor_sync(0xffffffffu, mx0, 2));
        mx1 = fmaxf(mx1, __shfl_xor_sync(0xffffffffu, mx1, 1));
        mx1 = fmaxf(mx1, __shfl_xor_sync(0xffffffffu, mx1, 2));
        float mn0 = fmaxf(ml[0], mx0);
        float mn1 = fmaxf(ml[1], mx1);
        float sc0 = __expf(ml[0] - mn0);
        float sc1 = __expf(ml[1] - mn1);

        uint32_t phi[16];
        float ps0 = 0.f, ps1 = 0.f;
#pragma unroll
        for (int ni = 0; ni < 8; ni++) {
            float p0 = __expf(pacc[ni][0] - mn0);
            float p1 = __expf(pacc[ni][1] - mn0);
            float p2 = __expf(pacc[ni][2] - mn1);
            float p3 = __expf(pacc[ni][3] - mn1);
            ps0 += p0 + p1;
            ps1 += p2 + p3;
            phi[2 * ni]     = pack_h2(p0, p1);
            phi[2 * ni + 1] = pack_h2(p2, p3);
        }
        ps0 += __shfl_xor_sync(0xffffffffu, ps0, 1);
        ps0 += __shfl_xor_sync(0xffffffffu, ps0, 2);
        ps1 += __shfl_xor_sync(0xffffffffu, ps1, 1);
        ps1 += __shfl_xor_sync(0xffffffffu, ps1, 2);
        ll[0] = ll[0] * sc0 + ps0;
        ll[1] = ll[1] * sc1 + ps1;
        ml[0] = mn0; ml[1] = mn1;
#pragma unroll
        for (int ni = 0; ni < 16; ni++) {
            oacc[ni][0] *= sc0; oacc[ni][1] *= sc0;
            oacc[ni][2] *= sc1; oacc[ni][3] *= sc1;
        }

#pragma unroll
        for (int ks = 0; ks < 4; ks++) {
            uint32_t aph[4] = { phi[4 * ks], phi[4 * ks + 1], phi[4 * ks + 2], phi[4 * ks + 3] };
#pragma unroll
            for (int db = 0; db < 8; db++) {
                uint32_t bh[4], bl[4];
                ldV(kvb + VHI_O, ks, db, bh);
                mma_f16(oacc[2 * db],     aph, bh);
                mma_f16(oacc[2 * db + 1], aph, bh + 2);
                ldV(kvb + VLO_O, ks, db, bl);
                mma_f16(oacc[2 * db],     aph, bl);
                mma_f16(oacc[2 * db + 1], aph, bl + 2);
            }
        }
        __syncthreads();
    }

    float inv0 = 1.0f / ll[0];
    float inv1 = 1.0f / ll[1];
    int row0 = qi * 128 + wrow + (lane >> 2);
#pragma unroll
    for (int ni = 0; ni < 16; ni++) {
        int col = h * HD + ni * 8 + (lane & 3) * 2;
        __half2 v0 = __floats2half2_rn(oacc[ni][0] * inv0, oacc[ni][1] * inv0);
        __half2 v1 = __floats2half2_rn(oacc[ni][2] * inv1, oacc[ni][3] * inv1);
        *(__half2*)(attn_out + (size_t)row0 * HID + col) = v0;
        *(__half2*)(attn_out + (size_t)(row0 + 8) * HID + col) = v1;
    }
}

// ---------------------------------------------------------------------------
extern "C" void kernel_launch(void* const* d_in, const int* in_sizes, int n_in,
                              void* d_out, int out_size) {
    const float* X  = (const float*)d_in[0];
    const float* Wq = (const float*)d_in[1];
    const float* Wk = (const float*)d_in[2];
    const float* Wv = (const float*)d_in[3];
    const float* Wo = (const float*)d_in[4];
    float* out = (float*)d_out;

    void* p;
    cudaGetSymbolAddress(&p, g_part);   float*  part  = (float*)p;
    cudaGetSymbolAddress(&p, g_attnh);  __half* attnh = (__half*)p;
    cudaGetSymbolAddress(&p, g_Xh);     __half* Xh    = (__half*)p;
    cudaGetSymbolAddress(&p, g_Wqkv2);  __half* Wqkv2 = (__half*)p;
    cudaGetSymbolAddress(&p, g_Wo2);    __half* Wo2   = (__half*)p;
    __half *Qh, *Kh, *Kl, *Vh, *Vl;
    cudaGetSymbolAddress(&p, g_Qh);  Qh = (__half*)p;
    cudaGetSymbolAddress(&p, g_Khi); Kh = (__half*)p;
    cudaGetSymbolAddress(&p, g_Klo); Kl = (__half*)p;
    cudaGetSymbolAddress(&p, g_Vhi); Vh = (__half*)p;
    cudaGetSymbolAddress(&p, g_Vlo); Vl = (__half*)p;

    cudaFuncSetAttribute(gemm_mma, cudaFuncAttributeMaxDynamicSharedMemorySize, GEMM_SMEM);
    cudaFuncSetAttribute(flash_mma, cudaFuncAttributeMaxDynamicSharedMemorySize, FLASH_SMEM);

    // all conversions in one launch
    convert_all<<<(CONV_N4 + 255) / 256, 256>>>(
        (const float4*)Wq, (const float4*)Wk, (const float4*)Wv,
        (const float4*)Wo, (const float4*)X);

    // QKV projection, split by term (z=0: hi half of K, z=1: lo half)
    gemm_mma<<<dim3(QKVW / 128, S_LEN / 128, 2), 256, GEMM_SMEM>>>(
        Xh, Wqkv2, part, QKVW, 32, (size_t)S_LEN * QKVW);

    // partial sum + RoPE + fp16 split
    rope_sum<<<dim3(S_LEN, NH + 2 * NKV), 64>>>(part, part + (size_t)S_LEN * QKVW);

    // HMMA causal flash attention -> fp16
    flash_mma<<<dim3(S_LEN / 128, NH), 256, FLASH_SMEM>>>(Qh, Kh, Kl, Vh, Vl, attnh);

    // Output projection (full K range, single z)
    gemm_mma<<<dim3(HID / 128, S_LEN / 128, 1), 256, GEMM_SMEM>>>(
        attnh, Wo2, out, HID, 64, 0);
}

// round 12
// speedup vs baseline: 1.0316x; 1.0316x over previous
#include <cuda_runtime.h>
#include <cuda_fp16.h>
#include <math.h>
#include <stdint.h>

// Problem constants
#define S_LEN  2048
#define HID    2048
#define NH     16
#define NKV    4
#define HD     128
#define KVDIM  512
#define QKVW   3072
#define K0     2048
#define KC2    (2*K0)      // 4096: B-side hi|lo concatenated K

// Scratch (device globals — no allocation allowed)
__device__ __half g_attnh[S_LEN * HID];          // attention output (fp16, A-side)
__device__ __half g_Xh[S_LEN * K0];              // X rounded fp16
__device__ __half g_Wqkv2[QKVW * KC2];           // Wq|Wk|Wv  [3072][hi|lo 4096]
__device__ __half g_Wo2[HID * KC2];              // Wo [2048][hi|lo 4096]
// attention operands
__device__ __half g_Qh[S_LEN * HID];             // scaled+rope q, rounded
__device__ __half g_Khi[S_LEN * KVDIM];
__device__ __half g_Klo[S_LEN * KVDIM];
__device__ __half g_Vhi[S_LEN * KVDIM];
__device__ __half g_Vlo[S_LEN * KVDIM];

// ---------------------------------------------------------------------------
// helpers
// ---------------------------------------------------------------------------
__device__ __forceinline__ uint32_t smem_u32(const void* p) {
    uint32_t a;
    asm("{ .reg .u64 t; cvta.to.shared.u64 t, %1; cvt.u32.u64 %0, t; }" : "=r"(a) : "l"(p));
    return a;
}
__device__ __forceinline__ void cpasync16(uint32_t s, const void* g) {
    asm volatile("cp.async.cg.shared.global [%0], [%1], 16;" :: "r"(s), "l"(g) : "memory");
}
__device__ __forceinline__ uint32_t swz(uint32_t off) {        // SW128 XOR swizzle
    return off ^ ((off >> 3) & 0x70);
}
__device__ __forceinline__ void ldsm4(uint32_t* r, uint32_t addr) {
    asm volatile("ldmatrix.sync.aligned.m8n8.x4.shared.b16 {%0,%1,%2,%3}, [%4];"
                 : "=r"(r[0]), "=r"(r[1]), "=r"(r[2]), "=r"(r[3]) : "r"(addr));
}
__device__ __forceinline__ void ldsm4t(uint32_t* r, uint32_t addr) {
    asm volatile("ldmatrix.sync.aligned.m8n8.x4.trans.shared.b16 {%0,%1,%2,%3}, [%4];"
                 : "=r"(r[0]), "=r"(r[1]), "=r"(r[2]), "=r"(r[3]) : "r"(addr));
}
__device__ __forceinline__ void mma_f16(float* d, const uint32_t* a, const uint32_t* b) {
    asm volatile(
        "mma.sync.aligned.m16n8k16.row.col.f32.f16.f16.f32 "
        "{%0,%1,%2,%3}, {%4,%5,%6,%7}, {%8,%9}, {%0,%1,%2,%3};"
        : "+f"(d[0]), "+f"(d[1]), "+f"(d[2]), "+f"(d[3])
        : "r"(a[0]), "r"(a[1]), "r"(a[2]), "r"(a[3]), "r"(b[0]), "r"(b[1]));
}
__device__ __forceinline__ uint32_t pack_h2(float lo, float hi) {
    __half2 t = __floats2half2_rn(lo, hi);
    return *reinterpret_cast<uint32_t*>(&t);
}

// ---------------------------------------------------------------------------
// One merged conversion kernel (row space: Wq|Wk|Wv|Wo|X, each row 2048 fp32)
// ---------------------------------------------------------------------------
#define CONV_N4 ((QKVW + HID + S_LEN) * (K0 / 4))

__global__ void convert_all(const float4* __restrict__ Wq, const float4* __restrict__ Wk,
                            const float4* __restrict__ Wv, const float4* __restrict__ Wo,
                            const float4* __restrict__ X) {
    int idx = blockIdx.x * 256 + threadIdx.x;
    if (idx >= CONV_N4) return;
    int e = idx * 4;
    int r = e >> 11;
    int c = e & (K0 - 1);

    if (r >= QKVW + HID) {           // X: plain fp16 round
        int xr = r - (QKVW + HID);
        float4 v = X[((size_t)xr * K0 + c) >> 2];
        __half2* o = (__half2*)(g_Xh + (size_t)xr * K0 + c);
        o[0] = __floats2half2_rn(v.x, v.y);
        o[1] = __floats2half2_rn(v.z, v.w);
        return;
    }

    const float4* src;
    __half* dst;
    if (r < HID) {
        src = Wq + (((size_t)r * K0 + c) >> 2);
        dst = g_Wqkv2 + (size_t)r * KC2;
    } else if (r < HID + KVDIM) {
        src = Wk + (((size_t)(r - HID) * K0 + c) >> 2);
        dst = g_Wqkv2 + (size_t)r * KC2;
    } else if (r < QKVW) {
        src = Wv + (((size_t)(r - HID - KVDIM) * K0 + c) >> 2);
        dst = g_Wqkv2 + (size_t)r * KC2;
    } else {
        src = Wo + (((size_t)(r - QKVW) * K0 + c) >> 2);
        dst = g_Wo2 + (size_t)(r - QKVW) * KC2;
    }
    float4 v = *src;
    __half2 h01 = __floats2half2_rn(v.x, v.y);
    __half2 h23 = __floats2half2_rn(v.z, v.w);
    __half2 l01 = __floats2half2_rn(v.x - __low2float(h01), v.y - __high2float(h01));
    __half2 l23 = __floats2half2_rn(v.z - __low2float(h23), v.w - __high2float(h23));
    __half2* oh = (__half2*)(dst + c);
    __half2* ol = (__half2*)(dst + K0 + c);
    oh[0] = h01; oh[1] = h23;
    ol[0] = l01; ol[1] = l23;
}

// ---------------------------------------------------------------------------
// fp16 HMMA GEMM, 2-term B-split (R9 proven): C[bm+128, bn+128] = A B'^T.
// CTA 128x128, KB=64, 8 warps (2x4), warp tile 64x32, 3-stage, 2 CTAs/SM.
// MODE 0: store fp32 C.  MODE 1: fused RoPE + fp16-split QKV epilogue.
// ---------------------------------------------------------------------------
#define KB      64
#define NKB     (KC2 / KB)          // 64
#define STG     32768
#define GEMM_SMEM (3 * STG)         // 98304
#define SCW     132

template <int MODE>
__global__ __launch_bounds__(256)
void gemm_mma(const __half* __restrict__ A, const __half* __restrict__ B,
              float* __restrict__ C, int ldc) {
    extern __shared__ char dsm[];
    const uint32_t base = smem_u32(dsm);
    const int tid  = threadIdx.x;
    const int wid  = tid >> 5;
    const int lane = tid & 31;
    const int wm   = wid >> 2;
    const int wn   = wid & 3;
    const int quad = lane >> 3;
    const int l8   = lane & 7;
    const int bm = blockIdx.y * 128;
    const int bn = blockIdx.x * 128;

    const __half* Abase = A + (size_t)bm * K0;
    const __half* Bbase = B + (size_t)bn * KC2;

    float acc[4][4][4];
#pragma unroll
    for (int i = 0; i < 4; i++)
#pragma unroll
        for (int j = 0; j < 4; j++)
#pragma unroll
            for (int v = 0; v < 4; v++) acc[i][j][v] = 0.f;

    int a_row[4], b_row[2];
#pragma unroll
    for (int mi = 0; mi < 4; mi++) a_row[mi] = wm * 64 + mi * 16 + (quad & 1) * 8 + l8;
#pragma unroll
    for (int n2 = 0; n2 < 2; n2++) b_row[n2] = wn * 32 + n2 * 16 + (quad >> 1) * 8 + l8;
    const int a_koff = (quad >> 1) * 16;
    const int b_koff = (quad & 1) * 16;

    const int ld_r = tid >> 3;
    const int ld_c = (tid & 7) * 8;

    auto issue_loads = [&](int kb, int buf) {
        const int a_col = (kb & 31) * KB + ld_c;
        const __half* ag = Abase + (size_t)ld_r * K0 + a_col;
        const __half* bg = Bbase + (size_t)ld_r * KC2 + kb * KB + ld_c;
        const uint32_t sa = base + buf * STG;
        const uint32_t sb = sa + 16384;
#pragma unroll
        for (int i = 0; i < 4; i++) {
            uint32_t s = swz((uint32_t)((ld_r + i * 32) * 128 + ld_c * 2));
            cpasync16(sa + s, ag + (size_t)i * 32 * K0);
            cpasync16(sb + s, bg + (size_t)i * 32 * KC2);
        }
        asm volatile("cp.async.commit_group;" ::: "memory");
    };

    issue_loads(0, 0);
    issue_loads(1, 1);

    for (int kb = 0; kb < NKB; kb++) {
        const int buf = kb % 3;
        if (kb + 2 < NKB) {
            issue_loads(kb + 2, (kb + 2) % 3);
            asm volatile("cp.async.wait_group 2;" ::: "memory");
        } else if (kb + 1 < NKB) {
            asm volatile("cp.async.wait_group 1;" ::: "memory");
        } else {
            asm volatile("cp.async.wait_group 0;" ::: "memory");
        }
        __syncthreads();

        const uint32_t As = base + buf * STG;
        const uint32_t Bs = As + 16384;
#pragma unroll
        for (int ks = 0; ks < 4; ks++) {
            uint32_t af[4][4], bf[2][4];
#pragma unroll
            for (int mi = 0; mi < 4; mi++)
                ldsm4(af[mi], As + swz((uint32_t)(a_row[mi] * 128 + ks * 32 + a_koff)));
#pragma unroll
            for (int n2 = 0; n2 < 2; n2++)
                ldsm4(bf[n2], Bs + swz((uint32_t)(b_row[n2] * 128 + ks * 32 + b_koff)));
#pragma unroll
            for (int mi = 0; mi < 4; mi++) {
#pragma unroll
                for (int ni = 0; ni < 4; ni++) {
                    uint32_t bb[2] = { bf[ni >> 1][(ni & 1) * 2], bf[ni >> 1][(ni & 1) * 2 + 1] };
                    mma_f16(acc[mi][ni], af[mi], bb);
                }
            }
        }
        __syncthreads();
    }

    const int er = lane >> 2;
    const int ec = (lane & 3) * 2;

    if (MODE == 0) {
#pragma unroll
        for (int mi = 0; mi < 4; mi++) {
            int row0 = bm + wm * 64 + mi * 16 + er;
#pragma unroll
            for (int ni = 0; ni < 4; ni++) {
                int col = bn + wn * 32 + ni * 8 + ec;
                *(float2*)(C + (size_t)row0 * ldc + col) = make_float2(acc[mi][ni][0], acc[mi][ni][1]);
                *(float2*)(C + (size_t)(row0 + 8) * ldc + col) = make_float2(acc[mi][ni][2], acc[mi][ni][3]);
            }
        }
    } else {
        // ---- QKV epilogue: stage 128x128 fp32 tile, RoPE + fp16 split ----
        float* sC = (float*)dsm;
        const int bx = blockIdx.x;                    // 0..23
        const int region = (bx < 16) ? 0 : (bx < 20 ? 1 : 2);   // Q / K / V
        const float sscale = 0.08838834764831845f;
        __syncthreads();
#pragma unroll
        for (int mi = 0; mi < 4; mi++) {
            int rr = wm * 64 + mi * 16 + er;
#pragma unroll
            for (int ni = 0; ni < 4; ni++) {
                int col = wn * 32 + ni * 8 + ec;
                sC[rr * SCW + col] = acc[mi][ni][0];
                sC[rr * SCW + col + 1] = acc[mi][ni][1];
                sC[(rr + 8) * SCW + col] = acc[mi][ni][2];
                sC[(rr + 8) * SCW + col + 1] = acc[mi][ni][3];
            }
        }
        __syncthreads();
#pragma unroll 4
        for (int it = 0; it < 32; it++) {
            int idx = tid + it * 256;                 // 8192 pairs
            int r = idx >> 6;
            int j = idx & 63;
            float x0 = sC[r * SCW + j];
            float x1 = sC[r * SCW + j + 64];
            int s = bm + r;
            if (region == 0) {
                float freq = powf(10000.0f, -(float)(2 * j) / (float)HD);
                float sn, cs;
                sincosf((float)s * freq, &sn, &cs);
                float y0 = (x0 * cs - x1 * sn) * sscale;
                float y1 = (x1 * cs + x0 * sn) * sscale;
                g_Qh[(size_t)s * HID + bn + j] = __float2half(y0);
                g_Qh[(size_t)s * HID + bn + j + 64] = __float2half(y1);
            } else if (region == 1) {
                float freq = powf(10000.0f, -(float)(2 * j) / (float)HD);
                float sn, cs;
                sincosf((float)s * freq, &sn, &cs);
                float y0 = x0 * cs - x1 * sn;
                float y1 = x1 * cs + x0 * sn;
                int kc = bn - HID + j;
                __half h0 = __float2half(y0), h1 = __float2half(y1);
                g_Khi[(size_t)s * KVDIM + kc] = h0;
                g_Khi[(size_t)s * KVDIM + kc + 64] = h1;
                g_Klo[(size_t)s * KVDIM + kc] = __float2half(y0 - __half2float(h0));
                g_Klo[(size_t)s * KVDIM + kc + 64] = __float2half(y1 - __half2float(h1));
            } else {
                int vc = bn - HID - KVDIM + j;
                __half h0 = __float2half(x0), h1 = __float2half(x1);
                g_Vhi[(size_t)s * KVDIM + vc] = h0;
                g_Vhi[(size_t)s * KVDIM + vc + 64] = h1;
                g_Vlo[(size_t)s * KVDIM + vc] = __float2half(x0 - __half2float(h0));
                g_Vlo[(size_t)s * KVDIM + vc + 64] = __float2half(x1 - __half2float(h1));
            }
        }
    }
}

// ---------------------------------------------------------------------------
// HMMA flash attention (causal, GQA), fp16 2-term.
// NEW geometry: CTA = 128 threads (4 warps), 64 q-rows; KV tile 32 rows,
// double-buffered. smem = Q 16KB + 2 x 32KB = 80KB -> 2 CTAs/SM.
// ---------------------------------------------------------------------------
#define Q_OFF 0
#define KVB_OFF(b) (16384 + (b) * 32768)
#define KHI_O 0
#define KLO_O 8192
#define VHI_O 16384
#define VLO_O 24576
#define FLASH_SMEM 81920

__global__ __launch_bounds__(128)
void flash_mma(const __half* __restrict__ Qp,
               const __half* __restrict__ Kh, const __half* __restrict__ Kl,
               const __half* __restrict__ Vh, const __half* __restrict__ Vl,
               __half* __restrict__ attn_out) {
    extern __shared__ char dsm[];
    const uint32_t base = smem_u32(dsm);
    const int tid  = threadIdx.x;
    const int lane = tid & 31;
    const int warp = tid >> 5;           // 0..3
    const int qt   = (int)gridDim.x - 1 - (int)blockIdx.x;   // big tiles first
    const int h    = blockIdx.y;
    const int kvh  = h >> 2;
    const int wrow = warp * 16;
    const int nt   = 2 * qt + 2;         // tiles of 32 kv rows
    const int q_row0 = qt * 64;

    const int rr = tid >> 4;             // 0..7
    const int cc = (tid & 15) * 8;       // 0..120
    const int panel = cc >> 6;
    const int col = cc & 63;

    // ---- Q load: 64 rows x 128 cols ----
    {
        const __half* qg = Qp + (size_t)q_row0 * HID + h * HD + cc;
#pragma unroll
        for (int i = 0; i < 8; i++) {
            int r = rr + i * 8;
            uint32_t d = panel * 8192 + swz((uint32_t)(r * 128 + col * 2));
            cpasync16(base + Q_OFF + d, qg + (size_t)r * HID);
        }
    }
    auto issue_kv = [&](int kb, int buf) {
        const uint32_t kvb = base + KVB_OFF(buf);
#pragma unroll
        for (int i = 0; i < 4; i++) {
            int r = rr + i * 8;          // 0..31
            uint32_t d = panel * 4096 + swz((uint32_t)(r * 128 + col * 2));
            size_t g = (size_t)(kb * 32 + r) * KVDIM + kvh * HD + cc;
            cpasync16(kvb + KHI_O + d, Kh + g);
            cpasync16(kvb + KLO_O + d, Kl + g);
            cpasync16(kvb + VHI_O + d, Vh + g);
            cpasync16(kvb + VLO_O + d, Vl + g);
        }
        asm volatile("cp.async.commit_group;" ::: "memory");
    };
    issue_kv(0, 0);
    asm volatile("cp.async.wait_group 0;" ::: "memory");
    __syncthreads();

    auto ldQ = [&](int ks, uint32_t* a) {
        int row = wrow + (lane & 15);
        int kc = (16 * ks) & 63;
        uint32_t addr = base + Q_OFF + (ks >> 2) * 8192 +
                        swz((uint32_t)(row * 128 + (kc + (lane >> 4) * 8) * 2));
        ldsm4(a, addr);
    };
    auto ldK = [&](uint32_t arr, int ks, int nb, uint32_t* b) {
        int row = nb * 16 + (lane & 7) + ((lane >> 4) << 3);   // 0..31
        int kc = (16 * ks) & 63;
        int kadd = ((lane >> 3) & 1) * 8;
        uint32_t addr = base + arr + (ks >> 2) * 4096 +
                        swz((uint32_t)(row * 128 + (kc + kadd) * 2));
        ldsm4(b, addr);
    };
    auto ldV = [&](uint32_t arr, int ks, int db, uint32_t* b) {
        int row = ks * 16 + (lane & 7) + (((lane >> 3) & 1) << 3);  // 0..31
        int dc = (16 * db) & 63;
        int dadd = (lane >> 4) * 8;
        uint32_t addr = base + arr + (db >> 2) * 4096 +
                        swz((uint32_t)(row * 128 + (dc + dadd) * 2));
        ldsm4t(b, addr);
    };

    float oacc[16][4];
#pragma unroll
    for (int i = 0; i < 16; i++)
#pragma unroll
        for (int v = 0; v < 4; v++) oacc[i][v] = 0.f;
    float ml[2] = {-1e30f, -1e30f};
    float ll[2] = {0.f, 0.f};

    for (int kb = 0; kb < nt; kb++) {
        const int buf = kb & 1;
        if (kb + 1 < nt) {
            issue_kv(kb + 1, buf ^ 1);
            asm volatile("cp.async.wait_group 1;" ::: "memory");
        } else {
            asm volatile("cp.async.wait_group 0;" ::: "memory");
        }
        __syncthreads();

        const uint32_t kvb = KVB_OFF(buf);

        // ---- scores: Q·Kh + Q·Kl over 32 kv rows ----
        float pacc[4][4];
#pragma unroll
        for (int i = 0; i < 4; i++)
#pragma unroll
            for (int v = 0; v < 4; v++) pacc[i][v] = 0.f;

#pragma unroll
        for (int ks = 0; ks < 8; ks++) {
            uint32_t aq[4];
            ldQ(ks, aq);
#pragma unroll
            for (int nb = 0; nb < 2; nb++) {
                uint32_t bh[4], bl[4];
                ldK(kvb + KHI_O, ks, nb, bh);
                ldK(kvb + KLO_O, ks, nb, bl);
                mma_f16(pacc[2 * nb],     aq, bh);
                mma_f16(pacc[2 * nb + 1], aq, bh + 2);
                mma_f16(pacc[2 * nb],     aq, bl);
                mma_f16(pacc[2 * nb + 1], aq, bl + 2);
            }
        }

        // ---- causal mask (diagonal tiles only: kb >= 2*qt) ----
        if (kb >= 2 * qt) {
            int r0 = q_row0 + wrow + (lane >> 2);
#pragma unroll
            for (int ni = 0; ni < 4; ni++) {
                int c0 = kb * 32 + ni * 8 + (lane & 3) * 2;
                if (c0     > r0)     pacc[ni][0] = -1e30f;
                if (c0 + 1 > r0)     pacc[ni][1] = -1e30f;
                if (c0     > r0 + 8) pacc[ni][2] = -1e30f;
                if (c0 + 1 > r0 + 8) pacc[ni][3] = -1e30f;
            }
        }

        // ---- online softmax ----
        float mx0 = -1e30f, mx1 = -1e30f;
#pragma unroll
        for (int ni = 0; ni < 4; ni++) {
            mx0 = fmaxf(mx0, fmaxf(pacc[ni][0], pacc[ni][1]));
            mx1 = fmaxf(mx1, fmaxf(pacc[ni][2], pacc[ni][3]));
        }
        mx0 = fmaxf(mx0, __shfl_xor_sync(0xffffffffu, mx0, 1));
        mx0 = fmaxf(mx0, __shfl_xor_sync(0xffffffffu, mx0, 2));
        mx1 = fmaxf(mx1, __shfl_xor_sync(0xffffffffu, mx1, 1));
        mx1 = fmaxf(mx1, __shfl_xor_sync(0xffffffffu, mx1, 2));
        float mn0 = fmaxf(ml[0], mx0);
        float mn1 = fmaxf(ml[1], mx1);
        float sc0 = __expf(ml[0] - mn0);
        float sc1 = __expf(ml[1] - mn1);

        uint32_t phi[8];
        float ps0 = 0.f, ps1 = 0.f;
#pragma unroll
        for (int ni = 0; ni < 4; ni++) {
            float p0 = __expf(pacc[ni][0] - mn0);
            float p1 = __expf(pacc[ni][1] - mn0);
            float p2 = __expf(pacc[ni][2] - mn1);
            float p3 = __expf(pacc[ni][3] - mn1);
            ps0 += p0 + p1;
            ps1 += p2 + p3;
            phi[2 * ni]     = pack_h2(p0, p1);
            phi[2 * ni + 1] = pack_h2(p2, p3);
        }
        ps0 += __shfl_xor_sync(0xffffffffu, ps0, 1);
        ps0 += __shfl_xor_sync(0xffffffffu, ps0, 2);
        ps1 += __shfl_xor_sync(0xffffffffu, ps1, 1);
        ps1 += __shfl_xor_sync(0xffffffffu, ps1, 2);
        ll[0] = ll[0] * sc0 + ps0;
        ll[1] = ll[1] * sc1 + ps1;
        ml[0] = mn0; ml[1] = mn1;
#pragma unroll
        for (int ni = 0; ni < 16; ni++) {
            oacc[ni][0] *= sc0; oacc[ni][1] *= sc0;
            oacc[ni][2] *= sc1; oacc[ni][3] *= sc1;
        }

        // ---- O += P·Vh + P·Vl  (2 k-steps of 16 over the 32 kv rows) ----
#pragma unroll
        for (int ks = 0; ks < 2; ks++) {
            uint32_t aph[4] = { phi[4 * ks], phi[4 * ks + 1], phi[4 * ks + 2], phi[4 * ks + 3] };
#pragma unroll
            for (int db = 0; db < 8; db++) {
                uint32_t bh[4], bl[4];
                ldV(kvb + VHI_O, ks, db, bh);
                mma_f16(oacc[2 * db],     aph, bh);
                mma_f16(oacc[2 * db + 1], aph, bh + 2);
                ldV(kvb + VLO_O, ks, db, bl);
                mma_f16(oacc[2 * db],     aph, bl);
                mma_f16(oacc[2 * db + 1], aph, bl + 2);
            }
        }
        __syncthreads();
    }

    // ---- epilogue: write fp16 ----
    float inv0 = 1.0f / ll[0];
    float inv1 = 1.0f / ll[1];
    int row0 = q_row0 + wrow + (lane >> 2);
#pragma unroll
    for (int ni = 0; ni < 16; ni++) {
        int col = h * HD + ni * 8 + (lane & 3) * 2;
        __half2 v0 = __floats2half2_rn(oacc[ni][0] * inv0, oacc[ni][1] * inv0);
        __half2 v1 = __floats2half2_rn(oacc[ni][2] * inv1, oacc[ni][3] * inv1);
        *(__half2*)(attn_out + (size_t)row0 * HID + col) = v0;
        *(__half2*)(attn_out + (size_t)(row0 + 8) * HID + col) = v1;
    }
}

// ---------------------------------------------------------------------------
extern "C" void kernel_launch(void* const* d_in, const int* in_sizes, int n_in,
                              void* d_out, int out_size) {
    const float* X  = (const float*)d_in[0];
    const float* Wq = (const float*)d_in[1];
    const float* Wk = (const float*)d_in[2];
    const float* Wv = (const float*)d_in[3];
    const float* Wo = (const float*)d_in[4];
    float* out = (float*)d_out;

    void* p;
    cudaGetSymbolAddress(&p, g_attnh);  __half* attnh = (__half*)p;
    cudaGetSymbolAddress(&p, g_Xh);     __half* Xh    = (__half*)p;
    cudaGetSymbolAddress(&p, g_Wqkv2);  __half* Wqkv2 = (__half*)p;
    cudaGetSymbolAddress(&p, g_Wo2);    __half* Wo2   = (__half*)p;
    __half *Qh, *Kh, *Kl, *Vh, *Vl;
    cudaGetSymbolAddress(&p, g_Qh);  Qh = (__half*)p;
    cudaGetSymbolAddress(&p, g_Khi); Kh = (__half*)p;
    cudaGetSymbolAddress(&p, g_Klo); Kl = (__half*)p;
    cudaGetSymbolAddress(&p, g_Vhi); Vh = (__half*)p;
    cudaGetSymbolAddress(&p, g_Vlo); Vl = (__half*)p;

    cudaFuncSetAttribute(gemm_mma<0>, cudaFuncAttributeMaxDynamicSharedMemorySize, GEMM_SMEM);
    cudaFuncSetAttribute(gemm_mma<1>, cudaFuncAttributeMaxDynamicSharedMemorySize, GEMM_SMEM);
    cudaFuncSetAttribute(flash_mma, cudaFuncAttributeMaxDynamicSharedMemorySize, FLASH_SMEM);

    // all conversions in one launch
    convert_all<<<(CONV_N4 + 255) / 256, 256>>>(
        (const float4*)Wq, (const float4*)Wk, (const float4*)Wv,
        (const float4*)Wo, (const float4*)X);

    // QKV projection with fused RoPE + split epilogue (R9 proven)
    gemm_mma<1><<<dim3(QKVW / 128, S_LEN / 128), 256, GEMM_SMEM>>>(Xh, Wqkv2, nullptr, 0);

    // HMMA causal flash attention -> fp16 (new: 2 CTAs/SM)
    flash_mma<<<dim3(S_LEN / 64, NH), 128, FLASH_SMEM>>>(Qh, Kh, Kl, Vh, Vl, attnh);

    // Output projection
    gemm_mma<0><<<dim3(HID / 128, S_LEN / 128), 256, GEMM_SMEM>>>(attnh, Wo2, out, HID);
}